// round 1
// baseline (speedup 1.0000x reference)
#include <cuda_runtime.h>

// HyperbolicResidualAdd: every intermediate vector lies in span{x_row, y_row}.
// Per row: reduce X2=x.x, Y2=y.y, XY=x.y; run the scalar coefficient chain;
// emit out = A*x + B*y. Single memory pass.

namespace {

constexpr int D    = 768;
constexpr int VEC  = D / 4;    // 192 float4 per row
constexpr int PL   = VEC / 32; // 6 float4 per lane

constexpr float EPSN      = 1e-15f;
constexpr float BALL_EPS  = 1e-5f;
constexpr float TARG_MAX  = 15.0f;
constexpr float ATANH_MAX = 1.0f - 1e-7f;

struct V2 { float a, b; };

__device__ __forceinline__ float softplusf(float v) {
    return (v > 20.f) ? v : log1pf(expf(v));
}

__device__ __forceinline__ float nrm(V2 v, float X2, float Y2, float XY) {
    float n2 = v.a * v.a * X2 + 2.f * v.a * v.b * XY + v.b * v.b * Y2;
    return fmaxf(sqrtf(fmaxf(n2, 0.f)), EPSN);
}

__device__ __forceinline__ float dotc(V2 v, V2 w, float X2, float Y2, float XY) {
    return v.a * w.a * X2 + (v.a * w.b + v.b * w.a) * XY + v.b * w.b * Y2;
}

__device__ __forceinline__ V2 scl(V2 v, float f) { return V2{v.a * f, v.b * f}; }

__device__ __forceinline__ V2 post_clip(V2 v, float X2, float Y2, float XY, float sc) {
    float n = nrm(v, X2, Y2, XY);
    float maxn = (1.0f - BALL_EPS) / sc;
    return scl(v, fminf(1.f, maxn / n));
}

__device__ __forceinline__ V2 pre_clip(V2 v, float X2, float Y2, float XY, float sc) {
    float n = nrm(v, X2, Y2, XY);
    float maxn = TARG_MAX / sc;
    return scl(v, fminf(1.f, maxn / n));
}

__device__ __forceinline__ V2 expmap0(V2 v, float X2, float Y2, float XY, float sc) {
    float n = nrm(v, X2, Y2, XY);
    return scl(v, tanhf(sc * n) / (sc * n));
}

__device__ __forceinline__ V2 mob_smul(float r, V2 v, float X2, float Y2, float XY, float sc) {
    float n = nrm(v, X2, Y2, XY);
    float t = atanhf(fminf(sc * n, ATANH_MAX));
    return scl(v, tanhf(r * t) / (sc * n));
}

__device__ __forceinline__ V2 mob_add(V2 v, V2 w, float X2, float Y2, float XY, float c) {
    float v2 = dotc(v, v, X2, Y2, XY);
    float w2 = dotc(w, w, X2, Y2, XY);
    float vw = dotc(v, w, X2, Y2, XY);
    float cv = 1.f + 2.f * c * vw + c * w2;   // coefficient on v
    float cw = 1.f - c * v2;                   // coefficient on w
    float den = fmaxf(1.f + 2.f * c * vw + c * c * v2 * w2, EPSN);
    float inv = 1.f / den;
    return V2{(cv * v.a + cw * w.a) * inv, (cv * v.b + cw * w.b) * inv};
}

__global__ void __launch_bounds__(256)
hyperres_kernel(const float* __restrict__ x, const float* __restrict__ y,
                const float* __restrict__ p_curv, const float* __restrict__ p_graw,
                const float* __restrict__ p_gscale, const float* __restrict__ p_scenter,
                float* __restrict__ out, int rows)
{
    int warp = (blockIdx.x * blockDim.x + threadIdx.x) >> 5;
    int lane = threadIdx.x & 31;
    if (warp >= rows) return;

    const float4* xr = reinterpret_cast<const float4*>(x) + (size_t)warp * VEC;
    const float4* yr = reinterpret_cast<const float4*>(y) + (size_t)warp * VEC;
    float4*       orow = reinterpret_cast<float4*>(out) + (size_t)warp * VEC;

    float4 xv[PL], yv[PL];
    float X2 = 0.f, Y2 = 0.f, XY = 0.f;

#pragma unroll
    for (int i = 0; i < PL; i++) {
        float4 a = xr[lane + i * 32];
        float4 b = yr[lane + i * 32];
        xv[i] = a; yv[i] = b;
        X2 += a.x * a.x + a.y * a.y + a.z * a.z + a.w * a.w;
        Y2 += b.x * b.x + b.y * b.y + b.z * b.z + b.w * b.w;
        XY += a.x * b.x + a.y * b.y + a.z * b.z + a.w * b.w;
    }
#pragma unroll
    for (int off = 16; off > 0; off >>= 1) {
        X2 += __shfl_xor_sync(0xffffffffu, X2, off);
        Y2 += __shfl_xor_sync(0xffffffffu, Y2, off);
        XY += __shfl_xor_sync(0xffffffffu, XY, off);
    }

    // ----- scalar parameter chain (SIMT-redundant across the warp) -----
    float c  = softplusf(__ldg(p_curv));
    float sc = sqrtf(c);
    float s  = 1.f / (1.f + expf(-__ldg(p_scenter)));
    float g_max = 1.f + softplusf(__ldg(p_gscale));
    float gamma = g_max * tanhf(__ldg(p_graw));

    V2 xc{1.f, 0.f}, yc{0.f, 1.f};

    V2 hrx = post_clip(expmap0(pre_clip(xc, X2, Y2, XY, sc), X2, Y2, XY, sc), X2, Y2, XY, sc);
    V2 hry = post_clip(expmap0(pre_clip(yc, X2, Y2, XY, sc), X2, Y2, XY, sc), X2, Y2, XY, sc);

    V2 sx = post_clip(mob_smul(s,       hrx, X2, Y2, XY, sc), X2, Y2, XY, sc);
    V2 sy = post_clip(mob_smul(1.f - s, hry, X2, Y2, XY, sc), X2, Y2, XY, sc);
    V2 p  = post_clip(mob_add(sx, sy, X2, Y2, XY, c), X2, Y2, XY, sc);

    V2 mp{-p.a, -p.b};
    V2 xp = post_clip(mob_add(mp, hrx, X2, Y2, XY, c), X2, Y2, XY, sc);
    V2 yp = post_clip(mob_add(mp, hry, X2, Y2, XY, c), X2, Y2, XY, sc);
    V2 ys = post_clip(mob_smul(gamma, yp, X2, Y2, XY, sc), X2, Y2, XY, sc);
    V2 hresp = post_clip(mob_add(xp, ys, X2, Y2, XY, c), X2, Y2, XY, sc);
    V2 hres  = mob_add(p, hresp, X2, Y2, XY, c);
    V2 r     = post_clip(hres, X2, Y2, XY, sc);

    // logmap0
    float nr = nrm(r, X2, Y2, XY);
    float fl = atanhf(fminf(sc * nr, ATANH_MAX)) / (sc * nr);
    float A = fl * r.a;
    float B = fl * r.b;

    // ----- emit out = A*x + B*y -----
#pragma unroll
    for (int i = 0; i < PL; i++) {
        float4 a = xv[i], b = yv[i], o;
        o.x = A * a.x + B * b.x;
        o.y = A * a.y + B * b.y;
        o.z = A * a.z + B * b.z;
        o.w = A * a.w + B * b.w;
        orow[lane + i * 32] = o;
    }
}

} // namespace

extern "C" void kernel_launch(void* const* d_in, const int* in_sizes, int n_in,
                              void* d_out, int out_size)
{
    const float* x       = (const float*)d_in[0];
    const float* y       = (const float*)d_in[1];
    const float* curv    = (const float*)d_in[2];
    const float* graw    = (const float*)d_in[3];
    const float* gscale  = (const float*)d_in[4];
    const float* scenter = (const float*)d_in[5];

    int rows = in_sizes[0] / D;          // 64*577 = 36928
    int warps_per_block = 8;             // 256 threads
    int blocks = (rows + warps_per_block - 1) / warps_per_block;

    hyperres_kernel<<<blocks, 256>>>(x, y, curv, graw, gscale, scenter,
                                     (float*)d_out, rows);
}

// round 2
// speedup vs baseline: 1.0250x; 1.0250x over previous
#include <cuda_runtime.h>

// HyperbolicResidualAdd: every intermediate vector lies in span{x_row, y_row}.
// Per row: reduce X2=x.x, Y2=y.y, XY=x.y; run the scalar coefficient chain;
// emit out = A*x + B*y. Single DRAM pass; x,y re-read from L1/L2 in the emit
// phase to keep register count low (occupancy >> latency hiding).

namespace {

constexpr int D    = 768;
constexpr int VEC  = D / 4;    // 192 float4 per row
constexpr int PL   = VEC / 32; // 6 float4 per lane

constexpr float EPSN      = 1e-15f;
constexpr float BALL_EPS  = 1e-5f;
constexpr float TARG_MAX  = 15.0f;
constexpr float ATANH_MAX = 1.0f - 1e-7f;

struct V2 { float a, b; };

__device__ __forceinline__ float softplusf(float v) {
    return (v > 20.f) ? v : log1pf(expf(v));
}

__device__ __forceinline__ float nrm(V2 v, float X2, float Y2, float XY) {
    float n2 = v.a * v.a * X2 + 2.f * v.a * v.b * XY + v.b * v.b * Y2;
    return fmaxf(sqrtf(fmaxf(n2, 0.f)), EPSN);
}

__device__ __forceinline__ float dotc(V2 v, V2 w, float X2, float Y2, float XY) {
    return v.a * w.a * X2 + (v.a * w.b + v.b * w.a) * XY + v.b * w.b * Y2;
}

__device__ __forceinline__ V2 scl(V2 v, float f) { return V2{v.a * f, v.b * f}; }

__device__ __forceinline__ V2 post_clip(V2 v, float X2, float Y2, float XY, float sc) {
    float n = nrm(v, X2, Y2, XY);
    float maxn = (1.0f - BALL_EPS) / sc;
    return scl(v, fminf(1.f, maxn / n));
}

__device__ __forceinline__ V2 pre_clip(V2 v, float X2, float Y2, float XY, float sc) {
    float n = nrm(v, X2, Y2, XY);
    float maxn = TARG_MAX / sc;
    return scl(v, fminf(1.f, maxn / n));
}

__device__ __forceinline__ V2 expmap0(V2 v, float X2, float Y2, float XY, float sc) {
    float n = nrm(v, X2, Y2, XY);
    return scl(v, tanhf(sc * n) / (sc * n));
}

__device__ __forceinline__ V2 mob_smul(float r, V2 v, float X2, float Y2, float XY, float sc) {
    float n = nrm(v, X2, Y2, XY);
    float t = atanhf(fminf(sc * n, ATANH_MAX));
    return scl(v, tanhf(r * t) / (sc * n));
}

__device__ __forceinline__ V2 mob_add(V2 v, V2 w, float X2, float Y2, float XY, float c) {
    float v2 = dotc(v, v, X2, Y2, XY);
    float w2 = dotc(w, w, X2, Y2, XY);
    float vw = dotc(v, w, X2, Y2, XY);
    float cv = 1.f + 2.f * c * vw + c * w2;   // coefficient on v
    float cw = 1.f - c * v2;                   // coefficient on w
    float den = fmaxf(1.f + 2.f * c * vw + c * c * v2 * w2, EPSN);
    float inv = 1.f / den;
    return V2{(cv * v.a + cw * w.a) * inv, (cv * v.b + cw * w.b) * inv};
}

__global__ void __launch_bounds__(256)
hyperres_kernel(const float* __restrict__ x, const float* __restrict__ y,
                const float* __restrict__ p_curv, const float* __restrict__ p_graw,
                const float* __restrict__ p_gscale, const float* __restrict__ p_scenter,
                float* __restrict__ out, int rows)
{
    int warp = (blockIdx.x * blockDim.x + threadIdx.x) >> 5;
    int lane = threadIdx.x & 31;
    if (warp >= rows) return;

    const float4* xr = reinterpret_cast<const float4*>(x) + (size_t)warp * VEC + lane;
    const float4* yr = reinterpret_cast<const float4*>(y) + (size_t)warp * VEC + lane;
    float4*       orow = reinterpret_cast<float4*>(out) + (size_t)warp * VEC + lane;

    float X2 = 0.f, Y2 = 0.f, XY = 0.f;

    // Phase 1: reductions. Do NOT keep row data in registers.
#pragma unroll
    for (int i = 0; i < PL; i++) {
        float4 a = xr[i * 32];
        float4 b = yr[i * 32];
        X2 = fmaf(a.x, a.x, fmaf(a.y, a.y, fmaf(a.z, a.z, fmaf(a.w, a.w, X2))));
        Y2 = fmaf(b.x, b.x, fmaf(b.y, b.y, fmaf(b.z, b.z, fmaf(b.w, b.w, Y2))));
        XY = fmaf(a.x, b.x, fmaf(a.y, b.y, fmaf(a.z, b.z, fmaf(a.w, b.w, XY))));
    }
#pragma unroll
    for (int off = 16; off > 0; off >>= 1) {
        X2 += __shfl_xor_sync(0xffffffffu, X2, off);
        Y2 += __shfl_xor_sync(0xffffffffu, Y2, off);
        XY += __shfl_xor_sync(0xffffffffu, XY, off);
    }

    // ----- scalar parameter chain (SIMT-redundant across the warp) -----
    float c  = softplusf(__ldg(p_curv));
    float sc = sqrtf(c);
    float s  = 1.f / (1.f + expf(-__ldg(p_scenter)));
    float g_max = 1.f + softplusf(__ldg(p_gscale));
    float gamma = g_max * tanhf(__ldg(p_graw));

    V2 xc{1.f, 0.f}, yc{0.f, 1.f};

    V2 hrx = post_clip(expmap0(pre_clip(xc, X2, Y2, XY, sc), X2, Y2, XY, sc), X2, Y2, XY, sc);
    V2 hry = post_clip(expmap0(pre_clip(yc, X2, Y2, XY, sc), X2, Y2, XY, sc), X2, Y2, XY, sc);

    V2 sx = post_clip(mob_smul(s,       hrx, X2, Y2, XY, sc), X2, Y2, XY, sc);
    V2 sy = post_clip(mob_smul(1.f - s, hry, X2, Y2, XY, sc), X2, Y2, XY, sc);
    V2 p  = post_clip(mob_add(sx, sy, X2, Y2, XY, c), X2, Y2, XY, sc);

    V2 mp{-p.a, -p.b};
    V2 xp = post_clip(mob_add(mp, hrx, X2, Y2, XY, c), X2, Y2, XY, sc);
    V2 yp = post_clip(mob_add(mp, hry, X2, Y2, XY, c), X2, Y2, XY, sc);
    V2 ys = post_clip(mob_smul(gamma, yp, X2, Y2, XY, sc), X2, Y2, XY, sc);
    V2 hresp = post_clip(mob_add(xp, ys, X2, Y2, XY, c), X2, Y2, XY, sc);
    V2 hres  = mob_add(p, hresp, X2, Y2, XY, c);
    V2 r     = post_clip(hres, X2, Y2, XY, sc);

    // logmap0
    float nr = nrm(r, X2, Y2, XY);
    float fl = atanhf(fminf(sc * nr, ATANH_MAX)) / (sc * nr);
    float A = fl * r.a;
    float B = fl * r.b;

    // Phase 2: re-read x,y (L1/L2 hits) and emit out = A*x + B*y.
#pragma unroll
    for (int i = 0; i < PL; i++) {
        float4 a = xr[i * 32];
        float4 b = yr[i * 32];
        float4 o;
        o.x = fmaf(A, a.x, B * b.x);
        o.y = fmaf(A, a.y, B * b.y);
        o.z = fmaf(A, a.z, B * b.z);
        o.w = fmaf(A, a.w, B * b.w);
        orow[i * 32] = o;
    }
}

} // namespace

extern "C" void kernel_launch(void* const* d_in, const int* in_sizes, int n_in,
                              void* d_out, int out_size)
{
    const float* x       = (const float*)d_in[0];
    const float* y       = (const float*)d_in[1];
    const float* curv    = (const float*)d_in[2];
    const float* graw    = (const float*)d_in[3];
    const float* gscale  = (const float*)d_in[4];
    const float* scenter = (const float*)d_in[5];

    int rows = in_sizes[0] / D;          // 64*577 = 36928
    int warps_per_block = 8;             // 256 threads
    int blocks = (rows + warps_per_block - 1) / warps_per_block;

    hyperres_kernel<<<blocks, 256>>>(x, y, curv, graw, gscale, scenter,
                                     (float*)d_out, rows);
}